// round 14
// baseline (speedup 1.0000x reference)
#include <cuda_runtime.h>
#include <math.h>
#include <stdint.h>

// Problem constants
#define B_      256
#define CIN     32
#define PEXP    192
#define COUT    32
#define HW_     1024
#define NPOS    (B_ * HW_)          // 262144 spatial-sample positions
#define EPS_BN  1e-5f

// ---------------- device scratch (no allocations allowed) ----------------
__device__ float  g_probs[3][16];
__device__ float  g_wmax[3][16];
__device__ float  g_W1t[128 * 192];        // [k=j*32+c][p], weights pre-divided by n_j
__device__ float  g_W2e[4 * 192 * 9];      // [(j*192+c)*9 + r], pre-divided by n_j
__device__ float  g_W3t[768 * 32];         // [k=c*4+j][o],    pre-divided by n_j
__device__ double g_sum0[192], g_sq0[192];
__device__ double g_sum1[192], g_sq1[192];
__device__ double g_sum2[32],  g_sq2[32];
__device__ float  g_sc0[192], g_bi0[192];
__device__ float  g_sc1[192], g_bi1[192];
__device__ float  g_sc2[32],  g_bi2[32];
__device__ float  g_y1[(size_t)B_ * PEXP * HW_];   // 201 MB raw layer1 output
__device__ float  g_y2[(size_t)B_ * PEXP * HW_];   // 201 MB raw layer2 output
__device__ float  g_y3[(size_t)B_ * COUT * HW_];   // 33 MB raw layer3 output

__device__ __constant__ float c_nf[4] = {3.f, 7.f, 15.f, 31.f};

// ---------------- prep kernels ----------------
__global__ void k_prep0(const float* p1, const float* p2, const float* p3) {
    int t = threadIdx.x;
    for (int i = t; i < 192; i += blockDim.x) { g_sum0[i] = 0.0; g_sq0[i] = 0.0; g_sum1[i] = 0.0; g_sq1[i] = 0.0; }
    for (int i = t; i < 32;  i += blockDim.x) { g_sum2[i] = 0.0; g_sq2[i] = 0.0; }
    if (t == 0) {
        const float* ps[3] = {p1, p2, p3};
        for (int l = 0; l < 3; l++) {
            float mx = -1e30f;
            for (int i = 0; i < 16; i++) mx = fmaxf(mx, ps[l][i]);
            float e[16], s = 0.f;
            for (int i = 0; i < 16; i++) { e[i] = expf(ps[l][i] - mx); s += e[i]; }
            for (int i = 0; i < 16; i++) g_probs[l][i] = e[i] / s;
        }
    }
}

__global__ void k_wmax(const float* w1, const float* w2, const float* w3) {
    int layer = blockIdx.x >> 4, cand = blockIdx.x & 15;
    const float* w; int n;
    if (layer == 0)      { w = w1 + cand * 6144; n = 6144; }
    else if (layer == 1) { w = w2 + cand * 1728; n = 1728; }
    else                 { w = w3 + cand * 6144; n = 6144; }
    float m = 0.f;
    for (int i = threadIdx.x; i < n; i += 256) m = fmaxf(m, fabsf(tanhf(w[i])));
    __shared__ float sm[256];
    sm[threadIdx.x] = m; __syncthreads();
    for (int s = 128; s > 0; s >>= 1) {
        if (threadIdx.x < s) sm[threadIdx.x] = fmaxf(sm[threadIdx.x], sm[threadIdx.x + s]);
        __syncthreads();
    }
    if (threadIdx.x == 0) g_wmax[layer][cand] = sm[0];
}

__device__ __forceinline__ float qw_val(float w, float mx, float n) {
    float t  = tanhf(w);
    float tn = t / (2.0f * mx) + 0.5f;
    float q  = rintf(tn * n) / n;
    return 2.0f * q - 1.0f;
}

__global__ void k_weff(const float* w1, const float* w2, const float* w3) {
    int e = blockIdx.x * blockDim.x + threadIdx.x;
    if (e < 24576) {                       // W1t: [k=j*32+c][p]
        int k = e / 192, p = e % 192, j = k >> 5, c = k & 31;
        float acc = 0.f;
        #pragma unroll
        for (int i = 0; i < 4; i++) {
            int idx = 4 * i + j;
            acc += g_probs[0][idx] * qw_val(w1[(idx * 192 + p) * 32 + c], g_wmax[0][idx], c_nf[i]);
        }
        g_W1t[e] = acc / c_nf[j];
    } else if (e < 24576 + 6912) {         // W2e: [(j*192+c)*9+r]
        int e2 = e - 24576;
        int j = e2 / 1728, rem = e2 % 1728, c = rem / 9, r = rem % 9;
        float acc = 0.f;
        #pragma unroll
        for (int i = 0; i < 4; i++) {
            int idx = 4 * i + j;
            acc += g_probs[1][idx] * qw_val(w2[idx * 1728 + c * 9 + r], g_wmax[1][idx], c_nf[i]);
        }
        g_W2e[e2] = acc / c_nf[j];
    } else if (e < 24576 + 6912 + 24576) { // W3t: [k=c*4+j][o]
        int e3 = e - 31488;
        int k = e3 >> 5, o = e3 & 31, c = k >> 2, j = k & 3;
        float acc = 0.f;
        #pragma unroll
        for (int i = 0; i < 4; i++) {
            int idx = 4 * i + j;
            acc += g_probs[2][idx] * qw_val(w3[(idx * 32 + o) * 192 + c], g_wmax[2][idx], c_nf[i]);
        }
        g_W3t[e3] = acc / c_nf[j];
    }
}

// ---------------- layer 1: 1x1 conv 32->192 as GEMM M=192, K=128, N=262144 ----------------
__global__ void __launch_bounds__(256) k_l1(const float* __restrict__ x) {
    __shared__ float sW[32 * 192];   // [c][p] for current j-chunk
    __shared__ float sA[32 * 64];    // [c][pos] quantized
    __shared__ float sX[32 * 64];    // [c][pos] raw saturated input, loaded once
    __shared__ float ssum[192], ssq[192];
    int t = threadIdx.x;
    int base = blockIdx.x * 64;
    int n = base >> 10, hw0 = base & 1023;
    const float* xb = x + (size_t)n * CIN * HW_ + hw0;
    int tx = t & 15, ty = t >> 4;    // pos = tx*4 + q ; p = ty*12 + pp
    float acc[48];
    #pragma unroll
    for (int i = 0; i < 48; i++) acc[i] = 0.f;
    for (int i = t; i < 192; i += 256) { ssum[i] = 0.f; ssq[i] = 0.f; }

    // load raw x tile once (saturate here; reused by all 4 bitwidth chunks)
    for (int i = t; i < 2048; i += 256) {
        int c = i >> 6, pl = i & 63;
        sX[i] = __saturatef(xb[c * HW_ + pl]);
    }

    for (int jc = 0; jc < 4; jc++) {
        float nj = c_nf[jc];
        if (jc > 0) __syncthreads();      // protect sA/sW reuse across chunks
        for (int i = t; i < 2048; i += 256)
            sA[i] = rintf(sX[i] * nj);
        const float4* wg = (const float4*)(g_W1t + jc * 32 * 192);
        for (int i = t; i < 1536; i += 256) ((float4*)sW)[i] = wg[i];
        __syncthreads();
        #pragma unroll
        for (int k = 0; k < 32; k++) {
            float4 a = *(const float4*)&sA[k * 64 + tx * 4];
            #pragma unroll
            for (int pw = 0; pw < 3; pw++) {
                float4 w = *(const float4*)&sW[k * 192 + ty * 12 + pw * 4];
                int b0 = pw * 16;
                acc[b0+0]  += w.x*a.x; acc[b0+1]  += w.x*a.y; acc[b0+2]  += w.x*a.z; acc[b0+3]  += w.x*a.w;
                acc[b0+4]  += w.y*a.x; acc[b0+5]  += w.y*a.y; acc[b0+6]  += w.y*a.z; acc[b0+7]  += w.y*a.w;
                acc[b0+8]  += w.z*a.x; acc[b0+9]  += w.z*a.y; acc[b0+10] += w.z*a.z; acc[b0+11] += w.z*a.w;
                acc[b0+12] += w.w*a.x; acc[b0+13] += w.w*a.y; acc[b0+14] += w.w*a.z; acc[b0+15] += w.w*a.w;
            }
        }
    }
    __syncthreads();
    #pragma unroll
    for (int pp = 0; pp < 12; pp++) {
        int p = ty * 12 + pp;
        float a0 = acc[pp*4+0], a1 = acc[pp*4+1], a2 = acc[pp*4+2], a3 = acc[pp*4+3];
        atomicAdd(&ssum[p], a0 + a1 + a2 + a3);
        atomicAdd(&ssq[p],  a0*a0 + a1*a1 + a2*a2 + a3*a3);
        float4 v = make_float4(a0, a1, a2, a3);
        *(float4*)(g_y1 + ((size_t)n * PEXP + p) * HW_ + hw0 + tx * 4) = v;
    }
    __syncthreads();
    for (int i = t; i < 192; i += 256) {
        atomicAdd(&g_sum0[i], (double)ssum[i]);
        atomicAdd(&g_sq0[i],  (double)ssq[i]);
    }
}

// ---------------- BN finalize ----------------
__global__ void k_fin(const float* __restrict__ g, const float* __restrict__ b, int layer) {
    int c = threadIdx.x;
    double *su, *sq; float *sc, *bi; int C;
    if (layer == 0)      { su = g_sum0; sq = g_sq0; sc = g_sc0; bi = g_bi0; C = 192; }
    else if (layer == 1) { su = g_sum1; sq = g_sq1; sc = g_sc1; bi = g_bi1; C = 192; }
    else                 { su = g_sum2; sq = g_sq2; sc = g_sc2; bi = g_bi2; C = 32; }
    if (c < C) {
        double m   = su[c] / (double)NPOS;
        double var = sq[c] / (double)NPOS - m * m;
        float r  = rsqrtf((float)var + EPS_BN);
        float s  = g[c] * r;
        sc[c] = s;
        bi[c] = b[c] - (float)m * s;
    }
}

// ---------------- layer 2: depthwise 3x3 over 192 ch, fused over 4 act-bitwidths ----------------
__global__ void __launch_bounds__(256) k_dw() {
    __shared__ float aq[2][4][34][34];   // zero-padded quantized planes
    __shared__ float sw[2][4][9];
    int t = threadIdx.x;
    int b = blockIdx.x;
    int n = b / 96, c0 = (b % 96) * 2;

    float* aqf = (float*)aq;
    for (int i = t; i < 2 * 4 * 34 * 34; i += 256) aqf[i] = 0.f;
    if (t < 72) {
        int ch = t / 36, j = (t % 36) / 9, r = t % 9;
        sw[ch][j][r] = g_W2e[(j * 192 + c0 + ch) * 9 + r];
    }
    __syncthreads();

    for (int ch = 0; ch < 2; ch++) {
        int c = c0 + ch;
        float scl = g_sc0[c], bia = g_bi0[c];
        const float* yb = g_y1 + ((size_t)n * PEXP + c) * HW_;
        for (int i = t; i < 1024; i += 256) {
            float v = fmaxf(fmaf(yb[i], scl, bia), 0.f);
            v = fminf(v, 1.f);
            int y = i >> 5, xx = i & 31;
            aq[ch][0][y + 1][xx + 1] = rintf(v * 3.f);
            aq[ch][1][y + 1][xx + 1] = rintf(v * 7.f);
            aq[ch][2][y + 1][xx + 1] = rintf(v * 15.f);
            aq[ch][3][y + 1][xx + 1] = rintf(v * 31.f);
        }
    }
    __syncthreads();

    int ch = t >> 7, g = t & 127;
    int row = g >> 2, x0 = (g & 3) * 8;
    int c = c0 + ch;
    float acc[8];
    #pragma unroll
    for (int o = 0; o < 8; o++) acc[o] = 0.f;
    #pragma unroll
    for (int j = 0; j < 4; j++) {
        float w0 = sw[ch][j][0], w1 = sw[ch][j][1], w2 = sw[ch][j][2];
        float w3 = sw[ch][j][3], w4 = sw[ch][j][4], w5 = sw[ch][j][5];
        float w6 = sw[ch][j][6], w7 = sw[ch][j][7], w8 = sw[ch][j][8];
        #pragma unroll
        for (int dy = 0; dy < 3; dy++) {
            float wa = (dy == 0) ? w0 : (dy == 1) ? w3 : w6;
            float wb = (dy == 0) ? w1 : (dy == 1) ? w4 : w7;
            float wc = (dy == 0) ? w2 : (dy == 1) ? w5 : w8;
            float r[10];
            #pragma unroll
            for (int q = 0; q < 10; q++) r[q] = aq[ch][j][row + dy][x0 + q];
            #pragma unroll
            for (int o = 0; o < 8; o++)
                acc[o] += r[o] * wa + r[o + 1] * wb + r[o + 2] * wc;
        }
    }
    // stats (warp-uniform channel)
    float s = 0.f, q = 0.f;
    #pragma unroll
    for (int o = 0; o < 8; o++) { s += acc[o]; q += acc[o] * acc[o]; }
    for (int off = 16; off > 0; off >>= 1) {
        s += __shfl_down_sync(0xFFFFFFFFu, s, off);
        q += __shfl_down_sync(0xFFFFFFFFu, q, off);
    }
    if ((t & 31) == 0) {
        atomicAdd(&g_sum1[c], (double)s);
        atomicAdd(&g_sq1[c],  (double)q);
    }
    float* yo = g_y2 + ((size_t)n * PEXP + c) * HW_ + row * 32 + x0;
    *(float4*)(yo + 0) = make_float4(acc[0], acc[1], acc[2], acc[3]);
    *(float4*)(yo + 4) = make_float4(acc[4], acc[5], acc[6], acc[7]);
}

// ---------------- layer 3: 1x1 conv 192->32 as GEMM M=32, K=768, N=262144 ----------------
__global__ void __launch_bounds__(256) k_l3() {
    __shared__ float sA[64 * 128];   // [k][pos], k = cl*4 + j within chunk
    __shared__ float sW[64 * 32];
    __shared__ float ssum[32], ssq[32];
    int t = threadIdx.x;
    int base = blockIdx.x * 128;
    int n = base >> 10, hw0 = base & 1023;
    int tx = t & 31, ty = t >> 5;    // pos = tx*4 + q ; p = ty*4 + pp
    float acc[16];
    #pragma unroll
    for (int i = 0; i < 16; i++) acc[i] = 0.f;
    if (t < 32) { ssum[t] = 0.f; ssq[t] = 0.f; }

    for (int kc = 0; kc < 12; kc++) {
        int cbase = kc * 16;
        if (kc > 0) __syncthreads();
        for (int i = t; i < 2048; i += 256) {
            int cl = i >> 7, pl = i & 127;
            int c = cbase + cl;
            float v = fmaxf(fmaf(g_y2[((size_t)n * PEXP + c) * HW_ + hw0 + pl], g_sc1[c], g_bi1[c]), 0.f);
            v = fminf(v, 1.f);
            int kb = (cl * 4) * 128 + pl;
            sA[kb]       = rintf(v * 3.f);
            sA[kb + 128] = rintf(v * 7.f);
            sA[kb + 256] = rintf(v * 15.f);
            sA[kb + 384] = rintf(v * 31.f);
        }
        const float4* wg = (const float4*)(g_W3t + cbase * 4 * 32);
        for (int i = t; i < 512; i += 256) ((float4*)sW)[i] = wg[i];
        __syncthreads();
        #pragma unroll
        for (int k = 0; k < 64; k++) {
            float4 a = *(const float4*)&sA[k * 128 + tx * 4];
            float4 w = *(const float4*)&sW[k * 32 + ty * 4];
            acc[0]  += w.x*a.x; acc[1]  += w.x*a.y; acc[2]  += w.x*a.z; acc[3]  += w.x*a.w;
            acc[4]  += w.y*a.x; acc[5]  += w.y*a.y; acc[6]  += w.y*a.z; acc[7]  += w.y*a.w;
            acc[8]  += w.z*a.x; acc[9]  += w.z*a.y; acc[10] += w.z*a.z; acc[11] += w.z*a.w;
            acc[12] += w.w*a.x; acc[13] += w.w*a.y; acc[14] += w.w*a.z; acc[15] += w.w*a.w;
        }
    }
    __syncthreads();
    #pragma unroll
    for (int pp = 0; pp < 4; pp++) {
        int p = ty * 4 + pp;
        float a0 = acc[pp*4+0], a1 = acc[pp*4+1], a2 = acc[pp*4+2], a3 = acc[pp*4+3];
        atomicAdd(&ssum[p], a0 + a1 + a2 + a3);
        atomicAdd(&ssq[p],  a0*a0 + a1*a1 + a2*a2 + a3*a3);
        *(float4*)(g_y3 + ((size_t)n * COUT + p) * HW_ + hw0 + tx * 4) = make_float4(a0, a1, a2, a3);
    }
    __syncthreads();
    if (t < 32) {
        atomicAdd(&g_sum2[t], (double)ssum[t]);
        atomicAdd(&g_sq2[t],  (double)ssq[t]);
    }
}

// ---------------- output: BN3 + residual ----------------
__global__ void k_out(const float* __restrict__ x, float* __restrict__ out) {
    int i4 = blockIdx.x * blockDim.x + threadIdx.x;
    if (i4 >= (B_ * COUT * HW_) / 4) return;
    int c = (i4 >> 8) & 31;
    float sc = g_sc2[c], bi = g_bi2[c];
    float4 y  = ((const float4*)g_y3)[i4];
    float4 xv = ((const float4*)x)[i4];
    float4 o;
    o.x = fmaf(y.x, sc, bi) + xv.x;
    o.y = fmaf(y.y, sc, bi) + xv.y;
    o.z = fmaf(y.z, sc, bi) + xv.z;
    o.w = fmaf(y.w, sc, bi) + xv.w;
    ((float4*)out)[i4] = o;
}

// ---------------- launch ----------------
extern "C" void kernel_launch(void* const* d_in, const int* in_sizes, int n_in,
                              void* d_out, int out_size) {
    (void)in_sizes; (void)n_in; (void)out_size;
    const float* x  = (const float*)d_in[0];
    const float* w1 = (const float*)d_in[1];
    const float* w2 = (const float*)d_in[2];
    const float* w3 = (const float*)d_in[3];
    const float* p1 = (const float*)d_in[4];
    const float* p2 = (const float*)d_in[5];
    const float* p3 = (const float*)d_in[6];
    const float* g1 = (const float*)d_in[7];
    const float* b1 = (const float*)d_in[8];
    const float* g2 = (const float*)d_in[9];
    const float* b2 = (const float*)d_in[10];
    const float* g3 = (const float*)d_in[11];
    const float* b3 = (const float*)d_in[12];
    float* out = (float*)d_out;

    k_prep0<<<1, 256>>>(p1, p2, p3);
    k_wmax<<<48, 256>>>(w1, w2, w3);
    k_weff<<<(24576 + 6912 + 24576 + 255) / 256, 256>>>(w1, w2, w3);
    k_l1<<<NPOS / 64, 256>>>(x);
    k_fin<<<1, 192>>>(g1, b1, 0);
    k_dw<<<B_ * 96, 256>>>();
    k_fin<<<1, 192>>>(g2, b2, 1);
    k_l3<<<NPOS / 128, 256>>>();
    k_fin<<<1, 192>>>(g3, b3, 2);
    k_out<<<(B_ * COUT * HW_ / 4 + 255) / 256, 256>>>(x, out);
}

// round 15
// speedup vs baseline: 1.7038x; 1.7038x over previous
#include <cuda_runtime.h>
#include <math.h>
#include <stdint.h>

// Problem constants
#define B_      256
#define CIN     32
#define PEXP    192
#define COUT    32
#define HW_     1024
#define NPOS    (B_ * HW_)          // 262144 spatial-sample positions
#define EPS_BN  1e-5f

// ---------------- device scratch (no allocations allowed) ----------------
__device__ float  g_probs[3][16];
__device__ float  g_wmax[3][16];
__device__ float  g_W1t[128 * 192];        // [k=j*32+c][p], weights pre-divided by n_j
__device__ float  g_W2e[4 * 192 * 9];      // [(j*192+c)*9 + r], pre-divided by n_j
__device__ float  g_W3t[768 * 32];         // [k=c*4+j][o],    pre-divided by n_j
__device__ double g_sum0[192], g_sq0[192];
__device__ double g_sum1[192], g_sq1[192];
__device__ double g_sum2[32],  g_sq2[32];
__device__ float  g_sc0[192], g_bi0[192];
__device__ float  g_sc1[192], g_bi1[192];
__device__ float  g_sc2[32],  g_bi2[32];
__device__ float  g_y1[(size_t)B_ * PEXP * HW_];   // 201 MB raw layer1 output
__device__ float  g_y2[(size_t)B_ * PEXP * HW_];   // 201 MB raw layer2 output
__device__ float  g_y3[(size_t)B_ * COUT * HW_];   // 33 MB raw layer3 output

__device__ __constant__ float c_nf[4] = {3.f, 7.f, 15.f, 31.f};

// ---------------- prep kernels ----------------
__global__ void k_prep0(const float* p1, const float* p2, const float* p3) {
    int t = threadIdx.x;
    for (int i = t; i < 192; i += blockDim.x) { g_sum0[i] = 0.0; g_sq0[i] = 0.0; g_sum1[i] = 0.0; g_sq1[i] = 0.0; }
    for (int i = t; i < 32;  i += blockDim.x) { g_sum2[i] = 0.0; g_sq2[i] = 0.0; }
    if (t == 0) {
        const float* ps[3] = {p1, p2, p3};
        for (int l = 0; l < 3; l++) {
            float mx = -1e30f;
            for (int i = 0; i < 16; i++) mx = fmaxf(mx, ps[l][i]);
            float e[16], s = 0.f;
            for (int i = 0; i < 16; i++) { e[i] = expf(ps[l][i] - mx); s += e[i]; }
            for (int i = 0; i < 16; i++) g_probs[l][i] = e[i] / s;
        }
    }
}

__global__ void k_wmax(const float* w1, const float* w2, const float* w3) {
    int layer = blockIdx.x >> 4, cand = blockIdx.x & 15;
    const float* w; int n;
    if (layer == 0)      { w = w1 + cand * 6144; n = 6144; }
    else if (layer == 1) { w = w2 + cand * 1728; n = 1728; }
    else                 { w = w3 + cand * 6144; n = 6144; }
    float m = 0.f;
    for (int i = threadIdx.x; i < n; i += 256) m = fmaxf(m, fabsf(tanhf(w[i])));
    __shared__ float sm[256];
    sm[threadIdx.x] = m; __syncthreads();
    for (int s = 128; s > 0; s >>= 1) {
        if (threadIdx.x < s) sm[threadIdx.x] = fmaxf(sm[threadIdx.x], sm[threadIdx.x + s]);
        __syncthreads();
    }
    if (threadIdx.x == 0) g_wmax[layer][cand] = sm[0];
}

__device__ __forceinline__ float qw_val(float w, float mx, float n) {
    float t  = tanhf(w);
    float tn = t / (2.0f * mx) + 0.5f;
    float q  = rintf(tn * n) / n;
    return 2.0f * q - 1.0f;
}

__global__ void k_weff(const float* w1, const float* w2, const float* w3) {
    int e = blockIdx.x * blockDim.x + threadIdx.x;
    if (e < 24576) {                       // W1t: [k=j*32+c][p]
        int k = e / 192, p = e % 192, j = k >> 5, c = k & 31;
        float acc = 0.f;
        #pragma unroll
        for (int i = 0; i < 4; i++) {
            int idx = 4 * i + j;
            acc += g_probs[0][idx] * qw_val(w1[(idx * 192 + p) * 32 + c], g_wmax[0][idx], c_nf[i]);
        }
        g_W1t[e] = acc / c_nf[j];
    } else if (e < 24576 + 6912) {         // W2e: [(j*192+c)*9+r]
        int e2 = e - 24576;
        int j = e2 / 1728, rem = e2 % 1728, c = rem / 9, r = rem % 9;
        float acc = 0.f;
        #pragma unroll
        for (int i = 0; i < 4; i++) {
            int idx = 4 * i + j;
            acc += g_probs[1][idx] * qw_val(w2[idx * 1728 + c * 9 + r], g_wmax[1][idx], c_nf[i]);
        }
        g_W2e[e2] = acc / c_nf[j];
    } else if (e < 24576 + 6912 + 24576) { // W3t: [k=c*4+j][o]
        int e3 = e - 31488;
        int k = e3 >> 5, o = e3 & 31, c = k >> 2, j = k & 3;
        float acc = 0.f;
        #pragma unroll
        for (int i = 0; i < 4; i++) {
            int idx = 4 * i + j;
            acc += g_probs[2][idx] * qw_val(w3[(idx * 32 + o) * 192 + c], g_wmax[2][idx], c_nf[i]);
        }
        g_W3t[e3] = acc / c_nf[j];
    }
}

// ---------------- layer 1: 1x1 conv 32->192 as GEMM M=192, K=128, N=262144 ----------------
// 768 threads, per-thread 4 pos x 4 p (16 acc) -> ~38 regs -> 2 CTAs/SM (48 warps, 75% occ).
// Same block tile (64 pos x 192 p), same jc/k loop order as the passing 256-thread version:
// per-output FMA accumulation order is bit-identical, so rel_err is unchanged.
__global__ void __launch_bounds__(768, 2) k_l1(const float* __restrict__ x) {
    __shared__ float sW[32 * 192];   // [c][p] for current j-chunk
    __shared__ float sA[32 * 64];    // [c][pos] quantized
    __shared__ float sX[32 * 64];    // [c][pos] raw saturated input, loaded once
    __shared__ float ssum[192], ssq[192];
    int t = threadIdx.x;
    int base = blockIdx.x * 64;
    int n = base >> 10, hw0 = base & 1023;
    const float* xb = x + (size_t)n * CIN * HW_ + hw0;
    int tx = t & 15, ty = t >> 4;    // pos = tx*4 + q ; p = ty*4 + pp  (ty: 0..47)
    float acc[16];
    #pragma unroll
    for (int i = 0; i < 16; i++) acc[i] = 0.f;
    for (int i = t; i < 192; i += 768) { ssum[i] = 0.f; ssq[i] = 0.f; }

    // load raw x tile once (saturate here; reused by all 4 bitwidth chunks)
    for (int i = t; i < 2048; i += 768) {
        int c = i >> 6, pl = i & 63;
        sX[i] = __saturatef(xb[c * HW_ + pl]);
    }

    for (int jc = 0; jc < 4; jc++) {
        float nj = c_nf[jc];
        if (jc > 0) __syncthreads();      // protect sA/sW reuse across chunks
        for (int i = t; i < 2048; i += 768)
            sA[i] = rintf(sX[i] * nj);
        const float4* wg = (const float4*)(g_W1t + jc * 32 * 192);
        for (int i = t; i < 1536; i += 768) ((float4*)sW)[i] = wg[i];
        __syncthreads();
        #pragma unroll
        for (int k = 0; k < 32; k++) {
            float4 a = *(const float4*)&sA[k * 64 + tx * 4];
            float4 w = *(const float4*)&sW[k * 192 + ty * 4];
            acc[0]  += w.x*a.x; acc[1]  += w.x*a.y; acc[2]  += w.x*a.z; acc[3]  += w.x*a.w;
            acc[4]  += w.y*a.x; acc[5]  += w.y*a.y; acc[6]  += w.y*a.z; acc[7]  += w.y*a.w;
            acc[8]  += w.z*a.x; acc[9]  += w.z*a.y; acc[10] += w.z*a.z; acc[11] += w.z*a.w;
            acc[12] += w.w*a.x; acc[13] += w.w*a.y; acc[14] += w.w*a.z; acc[15] += w.w*a.w;
        }
    }
    __syncthreads();
    #pragma unroll
    for (int pp = 0; pp < 4; pp++) {
        int p = ty * 4 + pp;
        float a0 = acc[pp*4+0], a1 = acc[pp*4+1], a2 = acc[pp*4+2], a3 = acc[pp*4+3];
        atomicAdd(&ssum[p], a0 + a1 + a2 + a3);
        atomicAdd(&ssq[p],  a0*a0 + a1*a1 + a2*a2 + a3*a3);
        float4 v = make_float4(a0, a1, a2, a3);
        *(float4*)(g_y1 + ((size_t)n * PEXP + p) * HW_ + hw0 + tx * 4) = v;
    }
    __syncthreads();
    for (int i = t; i < 192; i += 768) {
        atomicAdd(&g_sum0[i], (double)ssum[i]);
        atomicAdd(&g_sq0[i],  (double)ssq[i]);
    }
}

// ---------------- BN finalize ----------------
__global__ void k_fin(const float* __restrict__ g, const float* __restrict__ b, int layer) {
    int c = threadIdx.x;
    double *su, *sq; float *sc, *bi; int C;
    if (layer == 0)      { su = g_sum0; sq = g_sq0; sc = g_sc0; bi = g_bi0; C = 192; }
    else if (layer == 1) { su = g_sum1; sq = g_sq1; sc = g_sc1; bi = g_bi1; C = 192; }
    else                 { su = g_sum2; sq = g_sq2; sc = g_sc2; bi = g_bi2; C = 32; }
    if (c < C) {
        double m   = su[c] / (double)NPOS;
        double var = sq[c] / (double)NPOS - m * m;
        float r  = rsqrtf((float)var + EPS_BN);
        float s  = g[c] * r;
        sc[c] = s;
        bi[c] = b[c] - (float)m * s;
    }
}

// ---------------- layer 2: depthwise 3x3 over 192 ch, fused over 4 act-bitwidths ----------------
__global__ void __launch_bounds__(256) k_dw() {
    __shared__ float aq[2][4][34][34];   // zero-padded quantized planes
    __shared__ float sw[2][4][9];
    int t = threadIdx.x;
    int b = blockIdx.x;
    int n = b / 96, c0 = (b % 96) * 2;

    float* aqf = (float*)aq;
    for (int i = t; i < 2 * 4 * 34 * 34; i += 256) aqf[i] = 0.f;
    if (t < 72) {
        int ch = t / 36, j = (t % 36) / 9, r = t % 9;
        sw[ch][j][r] = g_W2e[(j * 192 + c0 + ch) * 9 + r];
    }
    __syncthreads();

    for (int ch = 0; ch < 2; ch++) {
        int c = c0 + ch;
        float scl = g_sc0[c], bia = g_bi0[c];
        const float* yb = g_y1 + ((size_t)n * PEXP + c) * HW_;
        for (int i = t; i < 1024; i += 256) {
            float v = fmaxf(fmaf(yb[i], scl, bia), 0.f);
            v = fminf(v, 1.f);
            int y = i >> 5, xx = i & 31;
            aq[ch][0][y + 1][xx + 1] = rintf(v * 3.f);
            aq[ch][1][y + 1][xx + 1] = rintf(v * 7.f);
            aq[ch][2][y + 1][xx + 1] = rintf(v * 15.f);
            aq[ch][3][y + 1][xx + 1] = rintf(v * 31.f);
        }
    }
    __syncthreads();

    int ch = t >> 7, g = t & 127;
    int row = g >> 2, x0 = (g & 3) * 8;
    int c = c0 + ch;
    float acc[8];
    #pragma unroll
    for (int o = 0; o < 8; o++) acc[o] = 0.f;
    #pragma unroll
    for (int j = 0; j < 4; j++) {
        float w0 = sw[ch][j][0], w1 = sw[ch][j][1], w2 = sw[ch][j][2];
        float w3 = sw[ch][j][3], w4 = sw[ch][j][4], w5 = sw[ch][j][5];
        float w6 = sw[ch][j][6], w7 = sw[ch][j][7], w8 = sw[ch][j][8];
        #pragma unroll
        for (int dy = 0; dy < 3; dy++) {
            float wa = (dy == 0) ? w0 : (dy == 1) ? w3 : w6;
            float wb = (dy == 0) ? w1 : (dy == 1) ? w4 : w7;
            float wc = (dy == 0) ? w2 : (dy == 1) ? w5 : w8;
            float r[10];
            #pragma unroll
            for (int q = 0; q < 10; q++) r[q] = aq[ch][j][row + dy][x0 + q];
            #pragma unroll
            for (int o = 0; o < 8; o++)
                acc[o] += r[o] * wa + r[o + 1] * wb + r[o + 2] * wc;
        }
    }
    // stats (warp-uniform channel)
    float s = 0.f, q = 0.f;
    #pragma unroll
    for (int o = 0; o < 8; o++) { s += acc[o]; q += acc[o] * acc[o]; }
    for (int off = 16; off > 0; off >>= 1) {
        s += __shfl_down_sync(0xFFFFFFFFu, s, off);
        q += __shfl_down_sync(0xFFFFFFFFu, q, off);
    }
    if ((t & 31) == 0) {
        atomicAdd(&g_sum1[c], (double)s);
        atomicAdd(&g_sq1[c],  (double)q);
    }
    float* yo = g_y2 + ((size_t)n * PEXP + c) * HW_ + row * 32 + x0;
    *(float4*)(yo + 0) = make_float4(acc[0], acc[1], acc[2], acc[3]);
    *(float4*)(yo + 4) = make_float4(acc[4], acc[5], acc[6], acc[7]);
}

// ---------------- layer 3: 1x1 conv 192->32 as GEMM M=32, K=768, N=262144 ----------------
__global__ void __launch_bounds__(256) k_l3() {
    __shared__ float sA[64 * 128];   // [k][pos], k = cl*4 + j within chunk
    __shared__ float sW[64 * 32];
    __shared__ float ssum[32], ssq[32];
    int t = threadIdx.x;
    int base = blockIdx.x * 128;
    int n = base >> 10, hw0 = base & 1023;
    int tx = t & 31, ty = t >> 5;    // pos = tx*4 + q ; p = ty*4 + pp
    float acc[16];
    #pragma unroll
    for (int i = 0; i < 16; i++) acc[i] = 0.f;
    if (t < 32) { ssum[t] = 0.f; ssq[t] = 0.f; }

    for (int kc = 0; kc < 12; kc++) {
        int cbase = kc * 16;
        if (kc > 0) __syncthreads();
        for (int i = t; i < 2048; i += 256) {
            int cl = i >> 7, pl = i & 127;
            int c = cbase + cl;
            float v = fmaxf(fmaf(g_y2[((size_t)n * PEXP + c) * HW_ + hw0 + pl], g_sc1[c], g_bi1[c]), 0.f);
            v = fminf(v, 1.f);
            int kb = (cl * 4) * 128 + pl;
            sA[kb]       = rintf(v * 3.f);
            sA[kb + 128] = rintf(v * 7.f);
            sA[kb + 256] = rintf(v * 15.f);
            sA[kb + 384] = rintf(v * 31.f);
        }
        const float4* wg = (const float4*)(g_W3t + cbase * 4 * 32);
        for (int i = t; i < 512; i += 256) ((float4*)sW)[i] = wg[i];
        __syncthreads();
        #pragma unroll
        for (int k = 0; k < 64; k++) {
            float4 a = *(const float4*)&sA[k * 128 + tx * 4];
            float4 w = *(const float4*)&sW[k * 32 + ty * 4];
            acc[0]  += w.x*a.x; acc[1]  += w.x*a.y; acc[2]  += w.x*a.z; acc[3]  += w.x*a.w;
            acc[4]  += w.y*a.x; acc[5]  += w.y*a.y; acc[6]  += w.y*a.z; acc[7]  += w.y*a.w;
            acc[8]  += w.z*a.x; acc[9]  += w.z*a.y; acc[10] += w.z*a.z; acc[11] += w.z*a.w;
            acc[12] += w.w*a.x; acc[13] += w.w*a.y; acc[14] += w.w*a.z; acc[15] += w.w*a.w;
        }
    }
    __syncthreads();
    #pragma unroll
    for (int pp = 0; pp < 4; pp++) {
        int p = ty * 4 + pp;
        float a0 = acc[pp*4+0], a1 = acc[pp*4+1], a2 = acc[pp*4+2], a3 = acc[pp*4+3];
        atomicAdd(&ssum[p], a0 + a1 + a2 + a3);
        atomicAdd(&ssq[p],  a0*a0 + a1*a1 + a2*a2 + a3*a3);
        *(float4*)(g_y3 + ((size_t)n * COUT + p) * HW_ + hw0 + tx * 4) = make_float4(a0, a1, a2, a3);
    }
    __syncthreads();
    if (t < 32) {
        atomicAdd(&g_sum2[t], (double)ssum[t]);
        atomicAdd(&g_sq2[t],  (double)ssq[t]);
    }
}

// ---------------- output: BN3 + residual ----------------
__global__ void k_out(const float* __restrict__ x, float* __restrict__ out) {
    int i4 = blockIdx.x * blockDim.x + threadIdx.x;
    if (i4 >= (B_ * COUT * HW_) / 4) return;
    int c = (i4 >> 8) & 31;
    float sc = g_sc2[c], bi = g_bi2[c];
    float4 y  = ((const float4*)g_y3)[i4];
    float4 xv = ((const float4*)x)[i4];
    float4 o;
    o.x = fmaf(y.x, sc, bi) + xv.x;
    o.y = fmaf(y.y, sc, bi) + xv.y;
    o.z = fmaf(y.z, sc, bi) + xv.z;
    o.w = fmaf(y.w, sc, bi) + xv.w;
    ((float4*)out)[i4] = o;
}

// ---------------- launch ----------------
extern "C" void kernel_launch(void* const* d_in, const int* in_sizes, int n_in,
                              void* d_out, int out_size) {
    (void)in_sizes; (void)n_in; (void)out_size;
    const float* x  = (const float*)d_in[0];
    const float* w1 = (const float*)d_in[1];
    const float* w2 = (const float*)d_in[2];
    const float* w3 = (const float*)d_in[3];
    const float* p1 = (const float*)d_in[4];
    const float* p2 = (const float*)d_in[5];
    const float* p3 = (const float*)d_in[6];
    const float* g1 = (const float*)d_in[7];
    const float* b1 = (const float*)d_in[8];
    const float* g2 = (const float*)d_in[9];
    const float* b2 = (const float*)d_in[10];
    const float* g3 = (const float*)d_in[11];
    const float* b3 = (const float*)d_in[12];
    float* out = (float*)d_out;

    k_prep0<<<1, 256>>>(p1, p2, p3);
    k_wmax<<<48, 256>>>(w1, w2, w3);
    k_weff<<<(24576 + 6912 + 24576 + 255) / 256, 256>>>(w1, w2, w3);
    k_l1<<<NPOS / 64, 768>>>(x);
    k_fin<<<1, 192>>>(g1, b1, 0);
    k_dw<<<B_ * 96, 256>>>();
    k_fin<<<1, 192>>>(g2, b2, 1);
    k_l3<<<NPOS / 128, 256>>>();
    k_fin<<<1, 192>>>(g3, b3, 2);
    k_out<<<(B_ * COUT * HW_ / 4 + 255) / 256, 256>>>(x, out);
}